// round 15
// baseline (speedup 1.0000x reference)
#include <cuda_runtime.h>
#include <cuda_bf16.h>
#include <math.h>
#include <stdint.h>

// Problem constants
#define T_STEPS 1024
#define BATCH   16
#define DIMK    1024
#define HEADS   8
#define NDIM    64
#define HN      512                 // HEADS*NDIM
#define ROWS    (T_STEPS*BATCH)     // 16384
#define OUT_MAIN ((size_t)T_STEPS*BATCH*HN)        // 8388608
#define SFIN_ELEMS ((size_t)BATCH*HEADS*NDIM*NDIM) // 524288

// Scratch for the 4 projections (k,v,q,beta_sigmoided): 128 MB
__device__ float g_proj[4ull * ROWS * HN];

__device__ __forceinline__ float sigmoidf_acc(float v) {
    return 1.f / (1.f + expf(-v));
}

// ---------------------------------------------------------------------------
// bf16 split helpers: x = hi + lo (each bf16); 3-term mma recovers ~2^-18.
// Pairs packed along K: low 16 bits = even k, high 16 bits = odd k.
// ---------------------------------------------------------------------------
__device__ __forceinline__ void split_bf16_pair(float f0, float f1,
                                                uint32_t& hi, uint32_t& lo) {
    __nv_bfloat162 hp = __floats2bfloat162_rn(f0, f1);
    hi = *reinterpret_cast<uint32_t*>(&hp);
    float l0 = f0 - __low2float(hp);
    float l1 = f1 - __high2float(hp);
    __nv_bfloat162 lp = __floats2bfloat162_rn(l0, l1);
    lo = *reinterpret_cast<uint32_t*>(&lp);
}

__device__ __forceinline__ void mma_bf16(float c[4], const uint32_t a[4],
                                         const uint32_t b0, const uint32_t b1) {
    asm volatile(
        "mma.sync.aligned.m16n8k16.row.col.f32.bf16.bf16.f32 "
        "{%0,%1,%2,%3},{%4,%5,%6,%7},{%8,%9},{%0,%1,%2,%3};"
        : "+f"(c[0]), "+f"(c[1]), "+f"(c[2]), "+f"(c[3])
        : "r"(a[0]), "r"(a[1]), "r"(a[2]), "r"(a[3]), "r"(b0), "r"(b1));
}

__device__ __forceinline__ void ldm_x4(uint32_t r[4], uint32_t a) {
    asm volatile("ldmatrix.sync.aligned.m8n8.x4.shared.b16 {%0,%1,%2,%3}, [%4];"
                 : "=r"(r[0]), "=r"(r[1]), "=r"(r[2]), "=r"(r[3]) : "r"(a));
}

__device__ __forceinline__ uint32_t smem_u32(const void* p) {
    uint32_t a;
    asm("{ .reg .u64 t; cvta.to.shared.u64 t, %1; cvt.u32.u64 %0, t; }" : "=r"(a) : "l"(p));
    return a;
}

// 32B-row swizzle: XOR 16B-slot bits [4:5] with 128B-line bits [7:8].
#define SWZ(o) ((o) ^ ((((o) >> 7) & 3u) << 4))

// ---------------------------------------------------------------------------
// Projection GEMM: C = x @ W^T, 3x bf16 split. CTA 128x128, 128 threads,
// 4 warps with 64x64 warp tiles (2m x 2n) -> 96 mma per 16 ldmatrix.x4 per
// warp-chunk (1.5x better fragment reuse than 32x64). Staging: each thread
// owns one A row + one B row per chunk (4 LDG.128, 8 STS.128). occ 2.
// grid = (HN/128, ROWS/128, 4). z==3 applies sigmoid(+b_beta) in epilogue.
// ---------------------------------------------------------------------------
#define GBM 128
#define GBN 128
#define KF  16
#define STAGE_B 16384   // 4 tiles * 4KB
#define TILE_B  4096

__global__ __launch_bounds__(128, 2) void proj_gemm_bf16(
    const float* __restrict__ x,
    const float* __restrict__ Wk, const float* __restrict__ Wv,
    const float* __restrict__ Wq, const float* __restrict__ Wb,
    const float* __restrict__ b_beta)
{
    __shared__ __align__(128) uint32_t SM[2 * 4 * 1024];  // 32 KB

    const int z = blockIdx.z;
    const float* __restrict__ W = (z == 0) ? Wk : (z == 1) ? Wv : (z == 2) ? Wq : Wb;
    float* __restrict__ C = g_proj + (size_t)z * ROWS * HN;

    const uint32_t smb = smem_u32(SM);

    const int tid  = threadIdx.x;
    const int lane = tid & 31;
    const int wid  = tid >> 5;       // 0..3
    const int wm   = wid >> 1;       // 0..1 -> 64 rows
    const int wn   = wid & 1;        // 0..1 -> 64 cols
    const int g    = lane >> 2;      // 0..7
    const int tig  = lane & 3;       // 0..3

    const int m0 = blockIdx.y * GBM;
    const int n0 = blockIdx.x * GBN;

    // Staging: thread owns A row tid and B row tid (16 floats each per chunk)
    const float* xA = x + (size_t)(m0 + tid) * DIMK;
    const float* wB = W + (size_t)(n0 + tid) * DIMK;

    const uint32_t stOff0 = SWZ((uint32_t)(tid * 32));        // first 16B
    const uint32_t stOff1 = SWZ((uint32_t)(tid * 32 + 16));   // second 16B

    // ldmatrix lane-relative offsets (16 rows x 16B halves)
    const uint32_t aRel = (uint32_t)((lane & 15) * 32 + (lane >> 4) * 16);
    const uint32_t bRel = (uint32_t)((((lane & 7) + ((lane >> 4) << 3)) * 32)
                                     + (((lane >> 3) & 1) * 16));
    uint32_t adrA[4], adrB[4];
#pragma unroll
    for (int mi = 0; mi < 4; ++mi)
        adrA[mi] = SWZ((uint32_t)((wm * 64 + mi * 16) * 32) + aRel);
#pragma unroll
    for (int p = 0; p < 4; ++p)
        adrB[p] = SWZ((uint32_t)((wn * 64 + p * 16) * 32) + bRel);

    float c[4][8][4];
#pragma unroll
    for (int mi = 0; mi < 4; ++mi)
#pragma unroll
        for (int ni = 0; ni < 8; ++ni)
#pragma unroll
            for (int e = 0; e < 4; ++e) c[mi][ni][e] = 0.f;

    float4 ra[2], rb[2];   // 8 floats of A + 8 of B ... need 16: use 4 regs sets
    float4 ra2[2], rb2[2];

    auto load_chunk = [&](int koff) {
        ra[0]  = *(const float4*)(xA + koff);
        ra[1]  = *(const float4*)(xA + koff + 4);
        ra2[0] = *(const float4*)(xA + koff + 8);
        ra2[1] = *(const float4*)(xA + koff + 12);
        rb[0]  = *(const float4*)(wB + koff);
        rb[1]  = *(const float4*)(wB + koff + 4);
        rb2[0] = *(const float4*)(wB + koff + 8);
        rb2[1] = *(const float4*)(wB + koff + 12);
    };

    auto store_stage = [&](int s) {
        const float fa[16] = {ra[0].x, ra[0].y, ra[0].z, ra[0].w,
                              ra[1].x, ra[1].y, ra[1].z, ra[1].w,
                              ra2[0].x, ra2[0].y, ra2[0].z, ra2[0].w,
                              ra2[1].x, ra2[1].y, ra2[1].z, ra2[1].w};
        const float fb[16] = {rb[0].x, rb[0].y, rb[0].z, rb[0].w,
                              rb[1].x, rb[1].y, rb[1].z, rb[1].w,
                              rb2[0].x, rb2[0].y, rb2[0].z, rb2[0].w,
                              rb2[1].x, rb2[1].y, rb2[1].z, rb2[1].w};
        uint32_t h[8], l[8];
        char* base = (char*)SM + s * STAGE_B;
#pragma unroll
        for (int j = 0; j < 8; ++j) split_bf16_pair(fa[2 * j], fa[2 * j + 1], h[j], l[j]);
        *(uint4*)(base + 0 * TILE_B + stOff0) = make_uint4(h[0], h[1], h[2], h[3]);
        *(uint4*)(base + 0 * TILE_B + stOff1) = make_uint4(h[4], h[5], h[6], h[7]);
        *(uint4*)(base + 1 * TILE_B + stOff0) = make_uint4(l[0], l[1], l[2], l[3]);
        *(uint4*)(base + 1 * TILE_B + stOff1) = make_uint4(l[4], l[5], l[6], l[7]);
#pragma unroll
        for (int j = 0; j < 8; ++j) split_bf16_pair(fb[2 * j], fb[2 * j + 1], h[j], l[j]);
        *(uint4*)(base + 2 * TILE_B + stOff0) = make_uint4(h[0], h[1], h[2], h[3]);
        *(uint4*)(base + 2 * TILE_B + stOff1) = make_uint4(h[4], h[5], h[6], h[7]);
        *(uint4*)(base + 3 * TILE_B + stOff0) = make_uint4(l[0], l[1], l[2], l[3]);
        *(uint4*)(base + 3 * TILE_B + stOff1) = make_uint4(l[4], l[5], l[6], l[7]);
    };

    load_chunk(0);
    store_stage(0);
    __syncthreads();

    const int NCH = DIMK / KF;   // 64
    int buf = 0;
    for (int ch = 0; ch < NCH; ++ch) {
        if (ch + 1 < NCH) load_chunk((ch + 1) * KF);

        const uint32_t sOff = smb + buf * STAGE_B;

        uint32_t ah[4][4], al[4][4];
#pragma unroll
        for (int mi = 0; mi < 4; ++mi) {
            ldm_x4(ah[mi], sOff + 0 * TILE_B + adrA[mi]);
            ldm_x4(al[mi], sOff + 1 * TILE_B + adrA[mi]);
        }

#pragma unroll
        for (int p = 0; p < 4; ++p) {
            uint32_t bh[4], bl[4];
            ldm_x4(bh, sOff + 2 * TILE_B + adrB[p]);
            ldm_x4(bl, sOff + 3 * TILE_B + adrB[p]);
#pragma unroll
            for (int mi = 0; mi < 4; ++mi)
#pragma unroll
                for (int j = 0; j < 2; ++j) {
                    float* cc = c[mi][2 * p + j];
                    mma_bf16(cc, ah[mi], bh[2 * j], bh[2 * j + 1]);
                    mma_bf16(cc, ah[mi], bl[2 * j], bl[2 * j + 1]);
                    mma_bf16(cc, al[mi], bh[2 * j], bh[2 * j + 1]);
                }
        }

        if (ch + 1 < NCH) {
            store_stage(buf ^ 1);
            __syncthreads();
            buf ^= 1;
        }
    }

    // Epilogue: z==3 applies sigmoid(c + b_beta[col]).
#pragma unroll
    for (int mi = 0; mi < 4; ++mi) {
        const int r0 = m0 + wm * 64 + mi * 16 + g;
#pragma unroll
        for (int ni = 0; ni < 8; ++ni) {
            const int col = n0 + wn * 64 + ni * 8 + 2 * tig;
            float v0 = c[mi][ni][0], v1 = c[mi][ni][1];
            float v2 = c[mi][ni][2], v3 = c[mi][ni][3];
            if (z == 3) {
                const float bb0 = b_beta[col], bb1 = b_beta[col + 1];
                v0 = sigmoidf_acc(v0 + bb0);
                v1 = sigmoidf_acc(v1 + bb1);
                v2 = sigmoidf_acc(v2 + bb0);
                v3 = sigmoidf_acc(v3 + bb1);
            }
            float2* p0 = (float2*)&C[(size_t)r0 * HN + col];
            float2* p1 = (float2*)&C[(size_t)(r0 + 8) * HN + col];
            *p0 = make_float2(v0, v1);
            *p1 = make_float2(v2, v3);
        }
    }
}

// ---------------------------------------------------------------------------
// Fast device math
// ---------------------------------------------------------------------------
__device__ __forceinline__ float fast_ex2(float v) {
    float r;  asm("ex2.approx.f32 %0, %1;" : "=f"(r) : "f"(v));  return r;
}
__device__ __forceinline__ float fast_rcp(float v) {
    float r;  asm("rcp.approx.f32 %0, %1;" : "=f"(r) : "f"(v));  return r;
}
__device__ __forceinline__ float fast_rsqrt(float v) {
    float r;  asm("rsqrt.approx.f32 %0, %1;" : "=f"(r) : "f"(v));  return r;
}
__device__ __forceinline__ float fast_tanh(float x) {   // single MUFU.TANH
    float r;  asm("tanh.approx.f32 %0, %1;" : "=f"(r) : "f"(x));  return r;
}
__device__ __forceinline__ float fast_sigmoid(float x) {
    return fast_rcp(1.f + fast_ex2(x * -1.4426950408889634f));
}

// ---------------------------------------------------------------------------
// normalize_k (frozen): k <- k / ||k|| per (row, head).
// ---------------------------------------------------------------------------
__global__ __launch_bounds__(256, 8) void normalize_k()
{
    float* pk = g_proj;   // slab 0
    const int rowi = blockIdx.x;
    const int wid  = threadIdx.x >> 5;     // head
    const int lane = threadIdx.x & 31;

    float2* p = (float2*)(pk + (size_t)rowi * HN + wid * NDIM + lane * 2);
    float2 kk = *p;
    float ss = kk.x * kk.x + kk.y * kk.y;
#pragma unroll
    for (int o = 16; o > 0; o >>= 1)
        ss += __shfl_xor_sync(0xffffffffu, ss, o);
    const float inv = fast_rsqrt(ss + 1e-12f);
    kk.x *= inv;  kk.y *= inv;
    *p = kk;
}

// ---------------------------------------------------------------------------
// Barrier-free scan (frozen from R14, ~540us): 4 elements/thread. CTA = 128
// threads = 8 rows of one (b,h); grid = 1024 CTAs. 16-lane reduces.
// k pre-normalized. Prefetch distance 1.
// ---------------------------------------------------------------------------
__global__ __launch_bounds__(128, 8) void scan_kernel(
    const float* __restrict__ S0,
    float* __restrict__ out,
    float* __restrict__ Sfin)
{
    const int blk  = blockIdx.x;
    const int bh   = blk >> 3;
    const int rb   = blk & 7;
    const int b    = bh >> 3;
    const int h    = bh & 7;
    const int tid  = threadIdx.x;
    const int w    = tid >> 5;
    const int lane = tid & 31;
    const int row  = rb * 8 + w * 2 + (lane >> 4);   // 0..63
    const int jb   = (lane & 15) * 4;                // col base

    float S[4];
    const float* S0p = S0 + (size_t)bh * NDIM * NDIM + row * NDIM + jb;
#pragma unroll
    for (int e = 0; e < 4; ++e) S[e] = S0p[e];

    const size_t slab = (size_t)ROWS * HN;
    const size_t step = (size_t)BATCH * HN;
    const float* pk = g_proj + 0 * slab + (size_t)b * HN + h * NDIM;   // normalized
    const float* pv = g_proj + 1 * slab + (size_t)b * HN + h * NDIM;
    const float* pq = g_proj + 2 * slab + (size_t)b * HN + h * NDIM;
    const float* pb = g_proj + 3 * slab + (size_t)b * HN + h * NDIM;

    float4 kc = *(const float4*)(pk + jb);
    float4 qc = *(const float4*)(pq + jb);
    float  vc = pv[row];
    float  bc = pb[row];

    float* outp = out + (size_t)b * HN + h * NDIM + row;

    for (int t = 0; t < T_STEPS; ++t) {
        float4 kp, qp;
        float  vp = 0.f, bp = 0.f;
        if (t + 1 < T_STEPS) {
            const size_t o = (size_t)(t + 1) * step;
            kp = *(const float4*)(pk + o + jb);
            qp = *(const float4*)(pq + o + jb);
            vp = __ldg(pv + o + row);
            bp = __ldg(pb + o + row);
        } else {
            kp = kc; qp = qc;
        }

        const float kv[4] = {kc.x, kc.y, kc.z, kc.w};

        // rr = S_row . k_norm  (16-lane reduce)
        float r0 = fmaf(S[0], kv[0], 0.f);
        float r1 = fmaf(S[1], kv[1], 0.f);
        r0 = fmaf(S[2], kv[2], r0);
        r1 = fmaf(S[3], kv[3], r1);
        float rr = r0 + r1;
        rr += __shfl_xor_sync(0xffffffffu, rr, 1);
        rr += __shfl_xor_sync(0xffffffffu, rr, 2);
        rr += __shfl_xor_sync(0xffffffffu, rr, 4);
        rr += __shfl_xor_sync(0xffffffffu, rr, 8);

        const float delta = vc - rr;      // k unit-norm
        const float beta  = bc;

        const float qv[4] = {qc.x, qc.y, qc.z, qc.w};

        float acc = 0.f;
#pragma unroll
        for (int e = 0; e < 4; ++e) {
            float s = fast_tanh(fmaf(delta, kv[e], beta * S[e]));
            S[e] = s;
            acc = fmaf(s, qv[e], acc);
        }
        acc += __shfl_xor_sync(0xffffffffu, acc, 1);
        acc += __shfl_xor_sync(0xffffffffu, acc, 2);
        acc += __shfl_xor_sync(0xffffffffu, acc, 4);
        acc += __shfl_xor_sync(0xffffffffu, acc, 8);

        if ((lane & 15) == 0) {
            outp[(size_t)t * step] = acc * acc * fast_sigmoid(acc);
        }

        kc = kp; qc = qp; vc = vp; bc = bp;
    }

    if (Sfin != nullptr) {
        float* sp = Sfin + (size_t)bh * NDIM * NDIM + row * NDIM + jb;
#pragma unroll
        for (int e = 0; e < 4; ++e) sp[e] = S[e];
    }
}

// ---------------------------------------------------------------------------
// Inputs: x, S0, W_k, W_v, W_q, W_beta, b_beta
// ---------------------------------------------------------------------------
extern "C" void kernel_launch(void* const* d_in, const int* in_sizes, int n_in,
                              void* d_out, int out_size)
{
    const float* x   = (const float*)d_in[0];
    const float* S0  = (const float*)d_in[1];
    const float* Wk  = (const float*)d_in[2];
    const float* Wv  = (const float*)d_in[3];
    const float* Wq  = (const float*)d_in[4];
    const float* Wb  = (const float*)d_in[5];
    const float* bbt = (const float*)d_in[6];
    float* out = (float*)d_out;

    dim3 gg(HN / GBN, ROWS / GBM, 4);
    proj_gemm_bf16<<<gg, 128>>>(x, Wk, Wv, Wq, Wb, bbt);

    normalize_k<<<ROWS, 256>>>();

    float* sfin = nullptr;
    if ((size_t)out_size >= OUT_MAIN + SFIN_ELEMS) sfin = out + OUT_MAIN;

    scan_kernel<<<BATCH * HEADS * 8, 128>>>(S0, out, sfin);
}

// round 16
// speedup vs baseline: 1.1482x; 1.1482x over previous
#include <cuda_runtime.h>
#include <cuda_bf16.h>
#include <math.h>
#include <stdint.h>

// Problem constants
#define T_STEPS 1024
#define BATCH   16
#define DIMK    1024
#define HEADS   8
#define NDIM    64
#define HN      512                 // HEADS*NDIM
#define ROWS    (T_STEPS*BATCH)     // 16384
#define OUT_MAIN ((size_t)T_STEPS*BATCH*HN)        // 8388608
#define SFIN_ELEMS ((size_t)BATCH*HEADS*NDIM*NDIM) // 524288

// Scratch for the 4 projections (k_normalized,v,q,beta_sigmoided): 128 MB
__device__ float g_proj[4ull * ROWS * HN];

__device__ __forceinline__ float sigmoidf_acc(float v) {
    return 1.f / (1.f + expf(-v));
}

// ---------------------------------------------------------------------------
// Fast device math
// ---------------------------------------------------------------------------
__device__ __forceinline__ float fast_ex2(float v) {
    float r;  asm("ex2.approx.f32 %0, %1;" : "=f"(r) : "f"(v));  return r;
}
__device__ __forceinline__ float fast_rcp(float v) {
    float r;  asm("rcp.approx.f32 %0, %1;" : "=f"(r) : "f"(v));  return r;
}
__device__ __forceinline__ float fast_rsqrt(float v) {
    float r;  asm("rsqrt.approx.f32 %0, %1;" : "=f"(r) : "f"(v));  return r;
}
__device__ __forceinline__ float fast_tanh(float x) {   // single MUFU.TANH
    float r;  asm("tanh.approx.f32 %0, %1;" : "=f"(r) : "f"(x));  return r;
}
__device__ __forceinline__ float fast_sigmoid(float x) {
    return fast_rcp(1.f + fast_ex2(x * -1.4426950408889634f));
}

// ---------------------------------------------------------------------------
// bf16 split helpers: x = hi + lo (each bf16); 3-term mma recovers ~2^-18.
// Pairs packed along K: low 16 bits = even k, high 16 bits = odd k.
// ---------------------------------------------------------------------------
__device__ __forceinline__ void split_bf16_pair(float f0, float f1,
                                                uint32_t& hi, uint32_t& lo) {
    __nv_bfloat162 hp = __floats2bfloat162_rn(f0, f1);
    hi = *reinterpret_cast<uint32_t*>(&hp);
    float l0 = f0 - __low2float(hp);
    float l1 = f1 - __high2float(hp);
    __nv_bfloat162 lp = __floats2bfloat162_rn(l0, l1);
    lo = *reinterpret_cast<uint32_t*>(&lp);
}

__device__ __forceinline__ void mma_bf16(float c[4], const uint32_t a[4],
                                         const uint32_t b0, const uint32_t b1) {
    asm volatile(
        "mma.sync.aligned.m16n8k16.row.col.f32.bf16.bf16.f32 "
        "{%0,%1,%2,%3},{%4,%5,%6,%7},{%8,%9},{%0,%1,%2,%3};"
        : "+f"(c[0]), "+f"(c[1]), "+f"(c[2]), "+f"(c[3])
        : "r"(a[0]), "r"(a[1]), "r"(a[2]), "r"(a[3]), "r"(b0), "r"(b1));
}

__device__ __forceinline__ void ldm_x4(uint32_t r[4], uint32_t a) {
    asm volatile("ldmatrix.sync.aligned.m8n8.x4.shared.b16 {%0,%1,%2,%3}, [%4];"
                 : "=r"(r[0]), "=r"(r[1]), "=r"(r[2]), "=r"(r[3]) : "r"(a));
}

__device__ __forceinline__ uint32_t smem_u32(const void* p) {
    uint32_t a;
    asm("{ .reg .u64 t; cvta.to.shared.u64 t, %1; cvt.u32.u64 %0, t; }" : "=r"(a) : "l"(p));
    return a;
}

// 32B-row swizzle: XOR 16B-slot bits [4:5] with 128B-line bits [7:8].
#define SWZ(o) ((o) ^ ((((o) >> 7) & 3u) << 4))

// ---------------------------------------------------------------------------
// Projection GEMM (R14 config, ~636us): C = x @ W^T, 3x bf16 split.
// CTA 128x128, 256 threads (8 warps: 4m x 2n, warp tile 32x64), occ 2.
// Epilogue: z==3 applies sigmoid(+b_beta); z==0 normalizes each head-row of
// k in-register (a warp's 64 cols = exactly one head; a head-row lives in 4
// tig-lanes -> 2-shfl reduce) so no separate normalize pass is needed.
// ---------------------------------------------------------------------------
#define GBM 128
#define GBN 128
#define KF  16
#define STAGE_B 16384   // 4 tiles * 4KB
#define TILE_B  4096

__global__ __launch_bounds__(256, 2) void proj_gemm_bf16(
    const float* __restrict__ x,
    const float* __restrict__ Wk, const float* __restrict__ Wv,
    const float* __restrict__ Wq, const float* __restrict__ Wb,
    const float* __restrict__ b_beta)
{
    __shared__ __align__(128) uint32_t SM[2 * 4 * 1024];  // 32 KB

    const int z = blockIdx.z;
    const float* __restrict__ W = (z == 0) ? Wk : (z == 1) ? Wv : (z == 2) ? Wq : Wb;
    float* __restrict__ C = g_proj + (size_t)z * ROWS * HN;

    const uint32_t smb = smem_u32(SM);

    const int tid  = threadIdx.x;
    const int lane = tid & 31;
    const int wid  = tid >> 5;
    const int wm   = wid >> 1;        // 0..3 -> 32 rows
    const int wn   = wid & 1;         // 0..1 -> 64 cols (one full head)
    const int g    = lane >> 2;       // 0..7
    const int tig  = lane & 3;        // 0..3

    const int m0 = blockIdx.y * GBM;
    const int n0 = blockIdx.x * GBN;

    const int lm  = tid >> 1;
    const int lkf = (tid & 1) * 8;
    const float* xA = x + (size_t)(m0 + lm) * DIMK + lkf;
    const float* wB = W + (size_t)(n0 + lm) * DIMK + lkf;

    const uint32_t stOff = SWZ((uint32_t)(lm * 32 + (tid & 1) * 16));

    const uint32_t aRel = (uint32_t)((lane & 15) * 32 + (lane >> 4) * 16);
    const uint32_t bRel = (uint32_t)((((lane & 7) + ((lane >> 4) << 3)) * 32)
                                     + (((lane >> 3) & 1) * 16));
    uint32_t adrA[2], adrB[4];
#pragma unroll
    for (int mi = 0; mi < 2; ++mi)
        adrA[mi] = SWZ((uint32_t)((wm * 32 + mi * 16) * 32) + aRel);
#pragma unroll
    for (int p = 0; p < 4; ++p)
        adrB[p] = SWZ((uint32_t)((wn * 64 + p * 16) * 32) + bRel);

    float c[2][8][4];
#pragma unroll
    for (int mi = 0; mi < 2; ++mi)
#pragma unroll
        for (int ni = 0; ni < 8; ++ni)
#pragma unroll
            for (int e = 0; e < 4; ++e) c[mi][ni][e] = 0.f;

    float4 ra0 = *(const float4*)(xA);
    float4 ra1 = *(const float4*)(xA + 4);
    float4 rb0 = *(const float4*)(wB);
    float4 rb1 = *(const float4*)(wB + 4);

    auto store_stage = [&](int s, float4 a0, float4 a1, float4 b0, float4 b1) {
        const float fa[8] = {a0.x, a0.y, a0.z, a0.w, a1.x, a1.y, a1.z, a1.w};
        const float fb[8] = {b0.x, b0.y, b0.z, b0.w, b1.x, b1.y, b1.z, b1.w};
        uint32_t h[4], l[4];
        char* base = (char*)SM + s * STAGE_B + stOff;
#pragma unroll
        for (int j = 0; j < 4; ++j) split_bf16_pair(fa[2 * j], fa[2 * j + 1], h[j], l[j]);
        *(uint4*)(base + 0 * TILE_B) = make_uint4(h[0], h[1], h[2], h[3]);
        *(uint4*)(base + 1 * TILE_B) = make_uint4(l[0], l[1], l[2], l[3]);
#pragma unroll
        for (int j = 0; j < 4; ++j) split_bf16_pair(fb[2 * j], fb[2 * j + 1], h[j], l[j]);
        *(uint4*)(base + 2 * TILE_B) = make_uint4(h[0], h[1], h[2], h[3]);
        *(uint4*)(base + 3 * TILE_B) = make_uint4(l[0], l[1], l[2], l[3]);
    };

    store_stage(0, ra0, ra1, rb0, rb1);
    __syncthreads();

    const int NCH = DIMK / KF;   // 64
    int buf = 0;
    for (int ch = 0; ch < NCH; ++ch) {
        if (ch + 1 < NCH) {
            const size_t koff = (size_t)(ch + 1) * KF;
            ra0 = *(const float4*)(xA + koff);
            ra1 = *(const float4*)(xA + koff + 4);
            rb0 = *(const float4*)(wB + koff);
            rb1 = *(const float4*)(wB + koff + 4);
        }

        const uint32_t sOff = smb + buf * STAGE_B;

        uint32_t ah[2][4], al[2][4];
#pragma unroll
        for (int mi = 0; mi < 2; ++mi) {
            ldm_x4(ah[mi], sOff + 0 * TILE_B + adrA[mi]);
            ldm_x4(al[mi], sOff + 1 * TILE_B + adrA[mi]);
        }

#pragma unroll
        for (int p = 0; p < 4; ++p) {
            uint32_t bh[4], bl[4];
            ldm_x4(bh, sOff + 2 * TILE_B + adrB[p]);
            ldm_x4(bl, sOff + 3 * TILE_B + adrB[p]);
#pragma unroll
            for (int mi = 0; mi < 2; ++mi)
#pragma unroll
                for (int j = 0; j < 2; ++j) {
                    float* cc = c[mi][2 * p + j];
                    mma_bf16(cc, ah[mi], bh[2 * j], bh[2 * j + 1]);
                    mma_bf16(cc, ah[mi], bl[2 * j], bl[2 * j + 1]);
                    mma_bf16(cc, al[mi], bh[2 * j], bh[2 * j + 1]);
                }
        }

        if (ch + 1 < NCH) {
            store_stage(buf ^ 1, ra0, ra1, rb0, rb1);
            __syncthreads();
            buf ^= 1;
        }
    }

    // Epilogue.
#pragma unroll
    for (int mi = 0; mi < 2; ++mi) {
        const int r0 = m0 + wm * 32 + mi * 16 + g;

        float inv0 = 1.f, inv1 = 1.f;
        if (z == 0) {
            // ||k|| for rows r0 and r0+8 of this warp's head:
            // sum v0^2+v1^2 (row r0) and v2^2+v3^2 (row r0+8) over ni,
            // then reduce over the 4 tig lanes (lane = g*4 + tig).
            float ss0 = 0.f, ss1 = 0.f;
#pragma unroll
            for (int ni = 0; ni < 8; ++ni) {
                ss0 = fmaf(c[mi][ni][0], c[mi][ni][0], ss0);
                ss0 = fmaf(c[mi][ni][1], c[mi][ni][1], ss0);
                ss1 = fmaf(c[mi][ni][2], c[mi][ni][2], ss1);
                ss1 = fmaf(c[mi][ni][3], c[mi][ni][3], ss1);
            }
            ss0 += __shfl_xor_sync(0xffffffffu, ss0, 1);
            ss1 += __shfl_xor_sync(0xffffffffu, ss1, 1);
            ss0 += __shfl_xor_sync(0xffffffffu, ss0, 2);
            ss1 += __shfl_xor_sync(0xffffffffu, ss1, 2);
            inv0 = fast_rsqrt(ss0 + 1e-12f);
            inv1 = fast_rsqrt(ss1 + 1e-12f);
        }

#pragma unroll
        for (int ni = 0; ni < 8; ++ni) {
            const int col = n0 + wn * 64 + ni * 8 + 2 * tig;
            float v0 = c[mi][ni][0], v1 = c[mi][ni][1];
            float v2 = c[mi][ni][2], v3 = c[mi][ni][3];
            if (z == 0) {
                v0 *= inv0;  v1 *= inv0;
                v2 *= inv1;  v3 *= inv1;
            } else if (z == 3) {
                const float bb0 = b_beta[col], bb1 = b_beta[col + 1];
                v0 = sigmoidf_acc(v0 + bb0);
                v1 = sigmoidf_acc(v1 + bb1);
                v2 = sigmoidf_acc(v2 + bb0);
                v3 = sigmoidf_acc(v3 + bb1);
            }
            float2* p0 = (float2*)&C[(size_t)r0 * HN + col];
            float2* p1 = (float2*)&C[(size_t)(r0 + 8) * HN + col];
            *p0 = make_float2(v0, v1);
            *p1 = make_float2(v2, v3);
        }
    }
}

// ---------------------------------------------------------------------------
// Barrier-free scan (frozen from R14, ~540us): 4 elements/thread. CTA = 128
// threads = 8 rows of one (b,h); grid = 1024 CTAs. 16-lane reduces.
// k pre-normalized in the GEMM epilogue. Prefetch distance 1.
// ---------------------------------------------------------------------------
__global__ __launch_bounds__(128, 8) void scan_kernel(
    const float* __restrict__ S0,
    float* __restrict__ out,
    float* __restrict__ Sfin)
{
    const int blk  = blockIdx.x;
    const int bh   = blk >> 3;
    const int rb   = blk & 7;
    const int b    = bh >> 3;
    const int h    = bh & 7;
    const int tid  = threadIdx.x;
    const int w    = tid >> 5;
    const int lane = tid & 31;
    const int row  = rb * 8 + w * 2 + (lane >> 4);   // 0..63
    const int jb   = (lane & 15) * 4;                // col base

    float S[4];
    const float* S0p = S0 + (size_t)bh * NDIM * NDIM + row * NDIM + jb;
#pragma unroll
    for (int e = 0; e < 4; ++e) S[e] = S0p[e];

    const size_t slab = (size_t)ROWS * HN;
    const size_t step = (size_t)BATCH * HN;
    const float* pk = g_proj + 0 * slab + (size_t)b * HN + h * NDIM;   // normalized
    const float* pv = g_proj + 1 * slab + (size_t)b * HN + h * NDIM;
    const float* pq = g_proj + 2 * slab + (size_t)b * HN + h * NDIM;
    const float* pb = g_proj + 3 * slab + (size_t)b * HN + h * NDIM;

    float4 kc = *(const float4*)(pk + jb);
    float4 qc = *(const float4*)(pq + jb);
    float  vc = pv[row];
    float  bc = pb[row];

    float* outp = out + (size_t)b * HN + h * NDIM + row;

    for (int t = 0; t < T_STEPS; ++t) {
        float4 kp, qp;
        float  vp = 0.f, bp = 0.f;
        if (t + 1 < T_STEPS) {
            const size_t o = (size_t)(t + 1) * step;
            kp = *(const float4*)(pk + o + jb);
            qp = *(const float4*)(pq + o + jb);
            vp = __ldg(pv + o + row);
            bp = __ldg(pb + o + row);
        } else {
            kp = kc; qp = qc;
        }

        const float kv[4] = {kc.x, kc.y, kc.z, kc.w};

        // rr = S_row . k_norm  (16-lane reduce)
        float r0 = fmaf(S[0], kv[0], 0.f);
        float r1 = fmaf(S[1], kv[1], 0.f);
        r0 = fmaf(S[2], kv[2], r0);
        r1 = fmaf(S[3], kv[3], r1);
        float rr = r0 + r1;
        rr += __shfl_xor_sync(0xffffffffu, rr, 1);
        rr += __shfl_xor_sync(0xffffffffu, rr, 2);
        rr += __shfl_xor_sync(0xffffffffu, rr, 4);
        rr += __shfl_xor_sync(0xffffffffu, rr, 8);

        const float delta = vc - rr;      // k unit-norm
        const float beta  = bc;

        const float qv[4] = {qc.x, qc.y, qc.z, qc.w};

        float acc = 0.f;
#pragma unroll
        for (int e = 0; e < 4; ++e) {
            float s = fast_tanh(fmaf(delta, kv[e], beta * S[e]));
            S[e] = s;
            acc = fmaf(s, qv[e], acc);
        }
        acc += __shfl_xor_sync(0xffffffffu, acc, 1);
        acc += __shfl_xor_sync(0xffffffffu, acc, 2);
        acc += __shfl_xor_sync(0xffffffffu, acc, 4);
        acc += __shfl_xor_sync(0xffffffffu, acc, 8);

        if ((lane & 15) == 0) {
            outp[(size_t)t * step] = acc * acc * fast_sigmoid(acc);
        }

        kc = kp; qc = qp; vc = vp; bc = bp;
    }

    if (Sfin != nullptr) {
        float* sp = Sfin + (size_t)bh * NDIM * NDIM + row * NDIM + jb;
#pragma unroll
        for (int e = 0; e < 4; ++e) sp[e] = S[e];
    }
}

// ---------------------------------------------------------------------------
// Inputs: x, S0, W_k, W_v, W_q, W_beta, b_beta
// ---------------------------------------------------------------------------
extern "C" void kernel_launch(void* const* d_in, const int* in_sizes, int n_in,
                              void* d_out, int out_size)
{
    const float* x   = (const float*)d_in[0];
    const float* S0  = (const float*)d_in[1];
    const float* Wk  = (const float*)d_in[2];
    const float* Wv  = (const float*)d_in[3];
    const float* Wq  = (const float*)d_in[4];
    const float* Wb  = (const float*)d_in[5];
    const float* bbt = (const float*)d_in[6];
    float* out = (float*)d_out;

    dim3 gg(HN / GBN, ROWS / GBM, 4);
    proj_gemm_bf16<<<gg, 256>>>(x, Wk, Wv, Wq, Wb, bbt);

    float* sfin = nullptr;
    if ((size_t)out_size >= OUT_MAIN + SFIN_ELEMS) sfin = out + OUT_MAIN;

    scan_kernel<<<BATCH * HEADS * 8, 128>>>(S0, out, sfin);
}

// round 17
// speedup vs baseline: 1.1506x; 1.0021x over previous
#include <cuda_runtime.h>
#include <cuda_bf16.h>
#include <math.h>
#include <stdint.h>

// Problem constants
#define T_STEPS 1024
#define BATCH   16
#define DIMK    1024
#define HEADS   8
#define NDIM    64
#define HN      512                 // HEADS*NDIM
#define ROWS    (T_STEPS*BATCH)     // 16384
#define OUT_MAIN ((size_t)T_STEPS*BATCH*HN)        // 8388608
#define SFIN_ELEMS ((size_t)BATCH*HEADS*NDIM*NDIM) // 524288

// Scratch for the 4 projections (k_normalized,v,q,beta_sigmoided): 128 MB
__device__ float g_proj[4ull * ROWS * HN];

__device__ __forceinline__ float sigmoidf_acc(float v) {
    return 1.f / (1.f + expf(-v));
}

// ---------------------------------------------------------------------------
// Fast device math
// ---------------------------------------------------------------------------
__device__ __forceinline__ float fast_ex2(float v) {
    float r;  asm("ex2.approx.f32 %0, %1;" : "=f"(r) : "f"(v));  return r;
}
__device__ __forceinline__ float fast_rcp(float v) {
    float r;  asm("rcp.approx.f32 %0, %1;" : "=f"(r) : "f"(v));  return r;
}
__device__ __forceinline__ float fast_rsqrt(float v) {
    float r;  asm("rsqrt.approx.f32 %0, %1;" : "=f"(r) : "f"(v));  return r;
}
__device__ __forceinline__ float fast_tanh(float x) {   // single MUFU.TANH
    float r;  asm("tanh.approx.f32 %0, %1;" : "=f"(r) : "f"(x));  return r;
}
__device__ __forceinline__ float fast_sigmoid(float x) {
    return fast_rcp(1.f + fast_ex2(x * -1.4426950408889634f));
}

// ---------------------------------------------------------------------------
// bf16 split helpers: x = hi + lo (each bf16); 3-term mma recovers ~2^-18.
// Pairs packed along K: low 16 bits = even k, high 16 bits = odd k.
// ---------------------------------------------------------------------------
__device__ __forceinline__ void split_bf16_pair(float f0, float f1,
                                                uint32_t& hi, uint32_t& lo) {
    __nv_bfloat162 hp = __floats2bfloat162_rn(f0, f1);
    hi = *reinterpret_cast<uint32_t*>(&hp);
    float l0 = f0 - __low2float(hp);
    float l1 = f1 - __high2float(hp);
    __nv_bfloat162 lp = __floats2bfloat162_rn(l0, l1);
    lo = *reinterpret_cast<uint32_t*>(&lp);
}

__device__ __forceinline__ void mma_bf16(float c[4], const uint32_t a[4],
                                         const uint32_t b0, const uint32_t b1) {
    asm volatile(
        "mma.sync.aligned.m16n8k16.row.col.f32.bf16.bf16.f32 "
        "{%0,%1,%2,%3},{%4,%5,%6,%7},{%8,%9},{%0,%1,%2,%3};"
        : "+f"(c[0]), "+f"(c[1]), "+f"(c[2]), "+f"(c[3])
        : "r"(a[0]), "r"(a[1]), "r"(a[2]), "r"(a[3]), "r"(b0), "r"(b1));
}

__device__ __forceinline__ void ldm_x4(uint32_t r[4], uint32_t a) {
    asm volatile("ldmatrix.sync.aligned.m8n8.x4.shared.b16 {%0,%1,%2,%3}, [%4];"
                 : "=r"(r[0]), "=r"(r[1]), "=r"(r[2]), "=r"(r[3]) : "r"(a));
}

__device__ __forceinline__ uint32_t smem_u32(const void* p) {
    uint32_t a;
    asm("{ .reg .u64 t; cvta.to.shared.u64 t, %1; cvt.u32.u64 %0, t; }" : "=r"(a) : "l"(p));
    return a;
}

// 32B-row swizzle: XOR 16B-slot bits [4:5] with 128B-line bits [7:8].
#define SWZ(o) ((o) ^ ((((o) >> 7) & 3u) << 4))

// ---------------------------------------------------------------------------
// Projection GEMM (frozen from R16): C = x @ W^T, 3x bf16 split.
// CTA 128x128, 256 threads (8 warps: 4m x 2n, warp tile 32x64), occ 2.
// Epilogue: z==0 normalizes each head-row of k in-register; z==3 applies
// sigmoid(+b_beta).
// ---------------------------------------------------------------------------
#define GBM 128
#define GBN 128
#define KF  16
#define STAGE_B 16384   // 4 tiles * 4KB
#define TILE_B  4096

__global__ __launch_bounds__(256, 2) void proj_gemm_bf16(
    const float* __restrict__ x,
    const float* __restrict__ Wk, const float* __restrict__ Wv,
    const float* __restrict__ Wq, const float* __restrict__ Wb,
    const float* __restrict__ b_beta)
{
    __shared__ __align__(128) uint32_t SM[2 * 4 * 1024];  // 32 KB

    const int z = blockIdx.z;
    const float* __restrict__ W = (z == 0) ? Wk : (z == 1) ? Wv : (z == 2) ? Wq : Wb;
    float* __restrict__ C = g_proj + (size_t)z * ROWS * HN;

    const uint32_t smb = smem_u32(SM);

    const int tid  = threadIdx.x;
    const int lane = tid & 31;
    const int wid  = tid >> 5;
    const int wm   = wid >> 1;        // 0..3 -> 32 rows
    const int wn   = wid & 1;         // 0..1 -> 64 cols (one full head)
    const int g    = lane >> 2;       // 0..7
    const int tig  = lane & 3;        // 0..3

    const int m0 = blockIdx.y * GBM;
    const int n0 = blockIdx.x * GBN;

    const int lm  = tid >> 1;
    const int lkf = (tid & 1) * 8;
    const float* xA = x + (size_t)(m0 + lm) * DIMK + lkf;
    const float* wB = W + (size_t)(n0 + lm) * DIMK + lkf;

    const uint32_t stOff = SWZ((uint32_t)(lm * 32 + (tid & 1) * 16));

    const uint32_t aRel = (uint32_t)((lane & 15) * 32 + (lane >> 4) * 16);
    const uint32_t bRel = (uint32_t)((((lane & 7) + ((lane >> 4) << 3)) * 32)
                                     + (((lane >> 3) & 1) * 16));
    uint32_t adrA[2], adrB[4];
#pragma unroll
    for (int mi = 0; mi < 2; ++mi)
        adrA[mi] = SWZ((uint32_t)((wm * 32 + mi * 16) * 32) + aRel);
#pragma unroll
    for (int p = 0; p < 4; ++p)
        adrB[p] = SWZ((uint32_t)((wn * 64 + p * 16) * 32) + bRel);

    float c[2][8][4];
#pragma unroll
    for (int mi = 0; mi < 2; ++mi)
#pragma unroll
        for (int ni = 0; ni < 8; ++ni)
#pragma unroll
            for (int e = 0; e < 4; ++e) c[mi][ni][e] = 0.f;

    float4 ra0 = *(const float4*)(xA);
    float4 ra1 = *(const float4*)(xA + 4);
    float4 rb0 = *(const float4*)(wB);
    float4 rb1 = *(const float4*)(wB + 4);

    auto store_stage = [&](int s, float4 a0, float4 a1, float4 b0, float4 b1) {
        const float fa[8] = {a0.x, a0.y, a0.z, a0.w, a1.x, a1.y, a1.z, a1.w};
        const float fb[8] = {b0.x, b0.y, b0.z, b0.w, b1.x, b1.y, b1.z, b1.w};
        uint32_t h[4], l[4];
        char* base = (char*)SM + s * STAGE_B + stOff;
#pragma unroll
        for (int j = 0; j < 4; ++j) split_bf16_pair(fa[2 * j], fa[2 * j + 1], h[j], l[j]);
        *(uint4*)(base + 0 * TILE_B) = make_uint4(h[0], h[1], h[2], h[3]);
        *(uint4*)(base + 1 * TILE_B) = make_uint4(l[0], l[1], l[2], l[3]);
#pragma unroll
        for (int j = 0; j < 4; ++j) split_bf16_pair(fb[2 * j], fb[2 * j + 1], h[j], l[j]);
        *(uint4*)(base + 2 * TILE_B) = make_uint4(h[0], h[1], h[2], h[3]);
        *(uint4*)(base + 3 * TILE_B) = make_uint4(l[0], l[1], l[2], l[3]);
    };

    store_stage(0, ra0, ra1, rb0, rb1);
    __syncthreads();

    const int NCH = DIMK / KF;   // 64
    int buf = 0;
    for (int ch = 0; ch < NCH; ++ch) {
        if (ch + 1 < NCH) {
            const size_t koff = (size_t)(ch + 1) * KF;
            ra0 = *(const float4*)(xA + koff);
            ra1 = *(const float4*)(xA + koff + 4);
            rb0 = *(const float4*)(wB + koff);
            rb1 = *(const float4*)(wB + koff + 4);
        }

        const uint32_t sOff = smb + buf * STAGE_B;

        uint32_t ah[2][4], al[2][4];
#pragma unroll
        for (int mi = 0; mi < 2; ++mi) {
            ldm_x4(ah[mi], sOff + 0 * TILE_B + adrA[mi]);
            ldm_x4(al[mi], sOff + 1 * TILE_B + adrA[mi]);
        }

#pragma unroll
        for (int p = 0; p < 4; ++p) {
            uint32_t bh[4], bl[4];
            ldm_x4(bh, sOff + 2 * TILE_B + adrB[p]);
            ldm_x4(bl, sOff + 3 * TILE_B + adrB[p]);
#pragma unroll
            for (int mi = 0; mi < 2; ++mi)
#pragma unroll
                for (int j = 0; j < 2; ++j) {
                    float* cc = c[mi][2 * p + j];
                    mma_bf16(cc, ah[mi], bh[2 * j], bh[2 * j + 1]);
                    mma_bf16(cc, ah[mi], bl[2 * j], bl[2 * j + 1]);
                    mma_bf16(cc, al[mi], bh[2 * j], bh[2 * j + 1]);
                }
        }

        if (ch + 1 < NCH) {
            store_stage(buf ^ 1, ra0, ra1, rb0, rb1);
            __syncthreads();
            buf ^= 1;
        }
    }

    // Epilogue.
#pragma unroll
    for (int mi = 0; mi < 2; ++mi) {
        const int r0 = m0 + wm * 32 + mi * 16 + g;

        float inv0 = 1.f, inv1 = 1.f;
        if (z == 0) {
            float ss0 = 0.f, ss1 = 0.f;
#pragma unroll
            for (int ni = 0; ni < 8; ++ni) {
                ss0 = fmaf(c[mi][ni][0], c[mi][ni][0], ss0);
                ss0 = fmaf(c[mi][ni][1], c[mi][ni][1], ss0);
                ss1 = fmaf(c[mi][ni][2], c[mi][ni][2], ss1);
                ss1 = fmaf(c[mi][ni][3], c[mi][ni][3], ss1);
            }
            ss0 += __shfl_xor_sync(0xffffffffu, ss0, 1);
            ss1 += __shfl_xor_sync(0xffffffffu, ss1, 1);
            ss0 += __shfl_xor_sync(0xffffffffu, ss0, 2);
            ss1 += __shfl_xor_sync(0xffffffffu, ss1, 2);
            inv0 = fast_rsqrt(ss0 + 1e-12f);
            inv1 = fast_rsqrt(ss1 + 1e-12f);
        }

#pragma unroll
        for (int ni = 0; ni < 8; ++ni) {
            const int col = n0 + wn * 64 + ni * 8 + 2 * tig;
            float v0 = c[mi][ni][0], v1 = c[mi][ni][1];
            float v2 = c[mi][ni][2], v3 = c[mi][ni][3];
            if (z == 0) {
                v0 *= inv0;  v1 *= inv0;
                v2 *= inv1;  v3 *= inv1;
            } else if (z == 3) {
                const float bb0 = b_beta[col], bb1 = b_beta[col + 1];
                v0 = sigmoidf_acc(v0 + bb0);
                v1 = sigmoidf_acc(v1 + bb1);
                v2 = sigmoidf_acc(v2 + bb0);
                v3 = sigmoidf_acc(v3 + bb1);
            }
            float2* p0 = (float2*)&C[(size_t)r0 * HN + col];
            float2* p1 = (float2*)&C[(size_t)(r0 + 8) * HN + col];
            *p0 = make_float2(v0, v1);
            *p1 = make_float2(v2, v3);
        }
    }
}

// ---------------------------------------------------------------------------
// Barrier-free scan: 4 elements/thread, CTA = 64 threads (2 warps = 4 rows of
// one (b,h)); grid = 2048 CTAs (bh = blk>>4, rowblock rb = blk&15).
// Thread: row = rb*4 + 2*warp + (lane>>4); cols jb=(lane&15)*4..+3.
// 16-lane reduces. Smaller CTAs -> ~14 CTAs/SM resident -> ~7 warps/SMSP and
// fine-grained load balance across 148 SMs. k pre-normalized. Prefetch dist 1.
// ---------------------------------------------------------------------------
__global__ __launch_bounds__(64, 16) void scan_kernel(
    const float* __restrict__ S0,
    float* __restrict__ out,
    float* __restrict__ Sfin)
{
    const int blk  = blockIdx.x;
    const int bh   = blk >> 4;
    const int rb   = blk & 15;
    const int b    = bh >> 3;
    const int h    = bh & 7;
    const int tid  = threadIdx.x;
    const int w    = tid >> 5;
    const int lane = tid & 31;
    const int row  = rb * 4 + w * 2 + (lane >> 4);   // 0..63
    const int jb   = (lane & 15) * 4;                // col base

    float S[4];
    const float* S0p = S0 + (size_t)bh * NDIM * NDIM + row * NDIM + jb;
#pragma unroll
    for (int e = 0; e < 4; ++e) S[e] = S0p[e];

    const size_t slab = (size_t)ROWS * HN;
    const size_t step = (size_t)BATCH * HN;
    const float* pk = g_proj + 0 * slab + (size_t)b * HN + h * NDIM;   // normalized
    const float* pv = g_proj + 1 * slab + (size_t)b * HN + h * NDIM;
    const float* pq = g_proj + 2 * slab + (size_t)b * HN + h * NDIM;
    const float* pb = g_proj + 3 * slab + (size_t)b * HN + h * NDIM;

    float4 kc = *(const float4*)(pk + jb);
    float4 qc = *(const float4*)(pq + jb);
    float  vc = pv[row];
    float  bc = pb[row];

    float* outp = out + (size_t)b * HN + h * NDIM + row;

    for (int t = 0; t < T_STEPS; ++t) {
        float4 kp, qp;
        float  vp = 0.f, bp = 0.f;
        if (t + 1 < T_STEPS) {
            const size_t o = (size_t)(t + 1) * step;
            kp = *(const float4*)(pk + o + jb);
            qp = *(const float4*)(pq + o + jb);
            vp = __ldg(pv + o + row);
            bp = __ldg(pb + o + row);
        } else {
            kp = kc; qp = qc;
        }

        const float kv[4] = {kc.x, kc.y, kc.z, kc.w};

        // rr = S_row . k_norm  (16-lane reduce)
        float r0 = fmaf(S[0], kv[0], 0.f);
        float r1 = fmaf(S[1], kv[1], 0.f);
        r0 = fmaf(S[2], kv[2], r0);
        r1 = fmaf(S[3], kv[3], r1);
        float rr = r0 + r1;
        rr += __shfl_xor_sync(0xffffffffu, rr, 1);
        rr += __shfl_xor_sync(0xffffffffu, rr, 2);
        rr += __shfl_xor_sync(0xffffffffu, rr, 4);
        rr += __shfl_xor_sync(0xffffffffu, rr, 8);

        const float delta = vc - rr;      // k unit-norm
        const float beta  = bc;

        const float qv[4] = {qc.x, qc.y, qc.z, qc.w};

        float acc = 0.f;
#pragma unroll
        for (int e = 0; e < 4; ++e) {
            float s = fast_tanh(fmaf(delta, kv[e], beta * S[e]));
            S[e] = s;
            acc = fmaf(s, qv[e], acc);
        }
        acc += __shfl_xor_sync(0xffffffffu, acc, 1);
        acc += __shfl_xor_sync(0xffffffffu, acc, 2);
        acc += __shfl_xor_sync(0xffffffffu, acc, 4);
        acc += __shfl_xor_sync(0xffffffffu, acc, 8);

        if ((lane & 15) == 0) {
            outp[(size_t)t * step] = acc * acc * fast_sigmoid(acc);
        }

        kc = kp; qc = qp; vc = vp; bc = bp;
    }

    if (Sfin != nullptr) {
        float* sp = Sfin + (size_t)bh * NDIM * NDIM + row * NDIM + jb;
#pragma unroll
        for (int e = 0; e < 4; ++e) sp[e] = S[e];
    }
}

// ---------------------------------------------------------------------------
// Inputs: x, S0, W_k, W_v, W_q, W_beta, b_beta
// ---------------------------------------------------------------------------
extern "C" void kernel_launch(void* const* d_in, const int* in_sizes, int n_in,
                              void* d_out, int out_size)
{
    const float* x   = (const float*)d_in[0];
    const float* S0  = (const float*)d_in[1];
    const float* Wk  = (const float*)d_in[2];
    const float* Wv  = (const float*)d_in[3];
    const float* Wq  = (const float*)d_in[4];
    const float* Wb  = (const float*)d_in[5];
    const float* bbt = (const float*)d_in[6];
    float* out = (float*)d_out;

    dim3 gg(HN / GBN, ROWS / GBM, 4);
    proj_gemm_bf16<<<gg, 256>>>(x, Wk, Wv, Wq, Wb, bbt);

    float* sfin = nullptr;
    if ((size_t)out_size >= OUT_MAIN + SFIN_ELEMS) sfin = out + OUT_MAIN;

    scan_kernel<<<BATCH * HEADS * 16, 64>>>(S0, out, sfin);
}